// round 9
// baseline (speedup 1.0000x reference)
#include <cuda_runtime.h>
#include <math.h>

#define BF     512
#define NTOT   66
#define NOUT   50
#define KK     8
#define T_TOT  2048
#define TILE   32
#define NTILE  (T_TOT / TILE)
#define DT_F   0.05f
#define FPAD   68

// ---------------- constant tables -------------------------------------------
__device__ float g_band[17][NOUT];   // g_band[d][j] = POST[j+d][j+8]
__device__ float g_sneg[NTOT];       // -(float)s_full[n]

// ---------------- fast init: one block per output column ---------------------
__global__ void init_kernel() {
    __shared__ double s[NTOT], dl[NTOT], dm[NTOT], du[NTOT];
    __shared__ double r[2][NTOT];
    const int j   = blockIdx.x;      // 0..49
    const int tid = threadIdx.x;     // 0..95
    const double c = pow(1000.0, 1.0 / 49.0);

    if (tid < NTOT) {
        double tv = 0.1 * pow(c, (double)(tid - KK));
        s[tid] = (double)KK / tv;
        if (j == 0) g_sneg[tid] = -(float)s[tid];
    }
    __syncthreads();
    if (tid < NTOT) {
        if (tid >= 1 && tid <= NTOT - 2) {
            double denom = s[tid + 1] - s[tid - 1];
            dl[tid] = -(1.0 / c) / denom;
            dm[tid] = (1.0 / c - c) / denom;
            du[tid] = c / denom;
        } else {
            dl[tid] = dm[tid] = du[tid] = 0.0;
        }
        r[0][tid] = (tid == j + KK) ? 1.0 : 0.0;
    }
    __syncthreads();

    for (int k = 1; k <= KK; k++) {
        int src = (k - 1) & 1, dst = k & 1;
        if (tid < NTOT) {
            double acc = r[src][tid] * dm[tid];
            if (tid > 0)        acc += r[src][tid - 1] * du[tid - 1];
            if (tid < NTOT - 1) acc += r[src][tid + 1] * dl[tid + 1];
            r[dst][tid] = acc;
        }
        __syncthreads();
    }
    if (tid < 17) {
        int m = j + KK;
        double tau = 0.1 * pow(c, (double)(m - KK));
        double w = tau * exp(9.0 * log(s[m]) - lgamma(9.0));
        g_band[tid][j] = (float)(r[0][j + tid] * w);
    }
}

// ---------------- bit-exact logaddexp step -----------------------------------
__device__ __forceinline__ float laestep(float carry, float x, float lf, float sneg) {
    float a  = __fadd_rn(carry, __fmul_rn(x, sneg));
    float am = fmaxf(a, lf);
    float dd = __fsub_rn(a, lf);
    return __fadd_rn(am, log1pf(expf(-fabsf(dd))));
}

// ---------------- packed f32x2 helpers ----------------------------------------
__device__ __forceinline__ unsigned long long pack2(float lo, float hi) {
    unsigned long long u;
    asm("mov.b64 %0, {%1, %2};" : "=l"(u) : "f"(lo), "f"(hi));
    return u;
}
__device__ __forceinline__ unsigned long long fma2(unsigned long long a,
                                                   unsigned long long b,
                                                   unsigned long long c) {
    unsigned long long d;
    asm("fma.rn.f32x2 %0, %1, %2, %3;" : "=l"(d) : "l"(a), "l"(b), "l"(c));
    return d;
}

// matvec body for one row: 17-tap banded dot for columns (jj, jj+1)
__device__ __forceinline__ void mv_row(const float* __restrict__ Fr, int jj,
                                       const unsigned long long* __restrict__ C,
                                       size_t rb, float* __restrict__ til,
                                       float* __restrict__ Fout) {
    float2 v[9];
#pragma unroll
    for (int i = 0; i < 9; i++) v[i] = *(const float2*)(Fr + jj + 2 * i);
    unsigned long long acc = 0ULL;
#pragma unroll
    for (int i = 0; i < 17; i++) {
        unsigned long long p = (i & 1)
            ? pack2(v[i >> 1].y, v[(i >> 1) + 1].x)
            : pack2(v[i >> 1].x, v[i >> 1].y);
        acc = fma2(p, C[i], acc);
    }
    float a0, a1;
    asm("mov.b64 {%0, %1}, %2;" : "=f"(a0), "=f"(a1) : "l"(acc));
    __stcs((float2*)(til  + rb), make_float2(a0, a1));
    __stcs((float2*)(Fout + rb), v[4]);   // F lanes jj+8, jj+9
}

// ---------------- fused scan + banded einsum, 1 chain per block ---------------
__global__ void __launch_bounds__(160) main_kernel(
    const float* __restrict__ f, const float* __restrict__ alpha,
    const float* __restrict__ delta,
    float* __restrict__ til, float* __restrict__ hout, float* __restrict__ Fout) {
    __shared__ float2 shXL[2][TILE];          // (x, lf)
    __shared__ float  shF[2][TILE][FPAD];

    const int cb  = blockIdx.x;
    const int tid = threadIdx.x;

    // ---- roles ----
    const bool scanMain = (tid < 64);                 // w0,w1: lanes 0..63
    const bool xScan    = (tid >= 64 && tid < 66);    // lanes 64,65
    const bool isLoad   = (tid >= 66 && tid < 96);    // 30 loaders in w2
    const int  lt       = tid - 66;
    const int  mt       = tid - 96;                   // w3,w4
    const bool mvAct    = (tid >= 96) && (mt < 50);
    const int  jj       = mvAct ? 2 * (mt % 25) : 0;
    const int  rg       = mvAct ? (mt / 25) : 0;      // row parity

    float sneg = 0.0f, carry = -INFINITY;
    if (scanMain)   sneg = g_sneg[tid];
    else if (xScan) sneg = g_sneg[tid];               // 64,65 directly

    unsigned long long C[17];
    if (mvAct) {
#pragma unroll
        for (int d = 0; d < 17; d++)
            C[d] = pack2(g_band[d][jj], g_band[d][jj + 1]);
    }

    // ---- prologue: loaders fill tile 0 ----
    if (isLoad) {
#pragma unroll
        for (int rr = 0; rr < 2; rr++) {
            int row = lt + rr * 30;
            if (row < TILE) {
                size_t g = (size_t)row * BF + cb;
                float fv = __ldg(f + g);
                float av = __ldg(alpha + g);
                float dv = __ldg(delta + g);
                shXL[0][row] = make_float2(__fadd_rn(__fmul_rn(av, DT_F), dv),
                                           logf(__fmul_rn(fv, DT_F)));
            }
        }
    }
    __syncthreads();

    for (int k = 0; k < NTILE; k++) {
        const int cur = k & 1, prv = cur ^ 1;
        if (scanMain || xScan) {
#pragma unroll 8
            for (int j = 0; j < TILE; j++) {
                float2 v = shXL[cur][j];
                carry = laestep(carry, v.x, v.y, sneg);
                shF[cur][j][tid] = __expf(carry);
            }
        } else if (isLoad) {
            if (k + 1 < NTILE) {
                const int tn = (k + 1) * TILE;
#pragma unroll
                for (int rr = 0; rr < 2; rr++) {
                    int row = lt + rr * 30;
                    if (row < TILE) {
                        size_t g = (size_t)(tn + row) * BF + cb;
                        float fv = __ldg(f + g);
                        float av = __ldg(alpha + g);
                        float dv = __ldg(delta + g);
                        shXL[prv][row] = make_float2(__fadd_rn(__fmul_rn(av, DT_F), dv),
                                                     logf(__fmul_rn(fv, DT_F)));
                    }
                }
            }
        } else if (mvAct && k > 0) {
            const int t0 = (k - 1) * TILE;
            for (int row = rg; row < TILE; row += 2) {
                size_t rb = ((size_t)(t0 + row) * BF + cb) * NOUT + jj;
                mv_row(shF[prv][row], jj, C, rb, til, Fout);
            }
        }
        __syncthreads();
    }

    // ---- epilogue ----
    if (scanMain || xScan) {
        hout[(size_t)cb * NTOT + tid] = carry;
    } else if (mvAct) {
        const int t0 = (NTILE - 1) * TILE;
        const int buf = (NTILE - 1) & 1;
        for (int row = rg; row < TILE; row += 2) {
            size_t rb = ((size_t)(t0 + row) * BF + cb) * NOUT + jj;
            mv_row(shF[buf][row], jj, C, rb, til, Fout);
        }
    }
}

// ---------------- launch --------------------------------------------------------
extern "C" void kernel_launch(void* const* d_in, const int* in_sizes, int n_in,
                              void* d_out, int out_size) {
    const float* f     = (const float*)d_in[0];
    const float* alpha = (const float*)d_in[1];
    const float* delta = (const float*)d_in[2];

    float* out  = (float*)d_out;
    size_t tsz  = (size_t)T_TOT * BF * NOUT;
    float* til  = out;
    float* hptr = out + tsz;
    float* Fo   = out + tsz + (size_t)BF * NTOT;

    init_kernel<<<NOUT, 96>>>();
    main_kernel<<<BF, 160>>>(f, alpha, delta, til, hptr, Fo);
}

// round 10
// speedup vs baseline: 1.0004x; 1.0004x over previous
#include <cuda_runtime.h>
#include <math.h>

#define BF     512
#define NTOT   66
#define NOUT   50
#define KK     8
#define T_TOT  2048
#define TILE   32
#define NTILE  (T_TOT / TILE)
#define DT_F   0.05f
#define FPAD   68

// ---------------- constant tables -------------------------------------------
__device__ float g_band[17][NOUT];   // g_band[d][j] = POST[j+d][j+8]
__device__ float g_sneg[NTOT];       // -(float)s_full[n]

// ---------------- fast init: one block per output column ---------------------
__global__ void init_kernel() {
    __shared__ double s[NTOT], dl[NTOT], dm[NTOT], du[NTOT];
    __shared__ double r[2][NTOT];
    const int j   = blockIdx.x;      // 0..49
    const int tid = threadIdx.x;     // 0..95
    const double c = pow(1000.0, 1.0 / 49.0);

    if (tid < NTOT) {
        double tv = 0.1 * pow(c, (double)(tid - KK));
        s[tid] = (double)KK / tv;
        if (j == 0) g_sneg[tid] = -(float)s[tid];
    }
    __syncthreads();
    if (tid < NTOT) {
        if (tid >= 1 && tid <= NTOT - 2) {
            double denom = s[tid + 1] - s[tid - 1];
            dl[tid] = -(1.0 / c) / denom;
            dm[tid] = (1.0 / c - c) / denom;
            du[tid] = c / denom;
        } else {
            dl[tid] = dm[tid] = du[tid] = 0.0;
        }
        r[0][tid] = (tid == j + KK) ? 1.0 : 0.0;
    }
    __syncthreads();

    for (int k = 1; k <= KK; k++) {
        int src = (k - 1) & 1, dst = k & 1;
        if (tid < NTOT) {
            double acc = r[src][tid] * dm[tid];
            if (tid > 0)        acc += r[src][tid - 1] * du[tid - 1];
            if (tid < NTOT - 1) acc += r[src][tid + 1] * dl[tid + 1];
            r[dst][tid] = acc;
        }
        __syncthreads();
    }
    if (tid < 17) {
        int m = j + KK;
        double tau = 0.1 * pow(c, (double)(m - KK));
        double w = tau * exp(9.0 * log(s[m]) - lgamma(9.0));
        g_band[tid][j] = (float)(r[0][j + tid] * w);
    }
}

// ---------------- bit-exact logaddexp step -----------------------------------
__device__ __forceinline__ float laestep(float carry, float x, float lf, float sneg) {
    float a  = __fadd_rn(carry, __fmul_rn(x, sneg));
    float am = fmaxf(a, lf);
    float dd = __fsub_rn(a, lf);
    return __fadd_rn(am, log1pf(expf(-fabsf(dd))));
}

// ---------------- packed f32x2 helpers ----------------------------------------
__device__ __forceinline__ unsigned long long pack2(float lo, float hi) {
    unsigned long long u;
    asm("mov.b64 %0, {%1, %2};" : "=l"(u) : "f"(lo), "f"(hi));
    return u;
}
__device__ __forceinline__ unsigned long long fma2(unsigned long long a,
                                                   unsigned long long b,
                                                   unsigned long long c) {
    unsigned long long d;
    asm("fma.rn.f32x2 %0, %1, %2, %3;" : "=l"(d) : "l"(a), "l"(b), "l"(c));
    return d;
}

// matvec body for one row: 17-tap banded dot for columns (jj, jj+1)
__device__ __forceinline__ void mv_row(const float* __restrict__ Fr, int jj,
                                       const unsigned long long* __restrict__ C,
                                       size_t rb, float* __restrict__ til,
                                       float* __restrict__ Fout) {
    float2 v[9];
#pragma unroll
    for (int i = 0; i < 9; i++) v[i] = *(const float2*)(Fr + jj + 2 * i);
    unsigned long long acc = 0ULL;
#pragma unroll
    for (int i = 0; i < 17; i++) {
        unsigned long long p = (i & 1)
            ? pack2(v[i >> 1].y, v[(i >> 1) + 1].x)
            : pack2(v[i >> 1].x, v[i >> 1].y);
        acc = fma2(p, C[i], acc);
    }
    float a0, a1;
    asm("mov.b64 {%0, %1}, %2;" : "=f"(a0), "=f"(a1) : "l"(acc));
    __stcs((float2*)(til  + rb), make_float2(a0, a1));
    __stcs((float2*)(Fout + rb), v[4]);   // F lanes jj+8, jj+9
}

// ---------------- fused scan + banded einsum, 1 chain per block ---------------
__global__ void __launch_bounds__(160) main_kernel(
    const float* __restrict__ f, const float* __restrict__ alpha,
    const float* __restrict__ delta,
    float* __restrict__ til, float* __restrict__ hout, float* __restrict__ Fout) {
    __shared__ float2 shXL[2][TILE];          // (x, lf)
    __shared__ float  shF[2][TILE][FPAD];

    const int cb  = blockIdx.x;
    const int tid = threadIdx.x;

    // ---- roles ----
    const bool scanMain = (tid < 64);                 // w0,w1: lanes 0..63
    const bool xScan    = (tid >= 64 && tid < 66);    // lanes 64,65
    const bool isLoad   = (tid >= 66 && tid < 96);    // 30 loaders in w2
    const int  lt       = tid - 66;
    const int  mt       = tid - 96;                   // w3,w4
    const bool mvAct    = (tid >= 96) && (mt < 50);
    const int  jj       = mvAct ? 2 * (mt % 25) : 0;
    const int  rg       = mvAct ? (mt / 25) : 0;      // row parity

    float sneg = 0.0f, carry = -INFINITY;
    if (scanMain)   sneg = g_sneg[tid];
    else if (xScan) sneg = g_sneg[tid];               // 64,65 directly

    unsigned long long C[17];
    if (mvAct) {
#pragma unroll
        for (int d = 0; d < 17; d++)
            C[d] = pack2(g_band[d][jj], g_band[d][jj + 1]);
    }

    // ---- prologue: loaders fill tile 0 ----
    if (isLoad) {
#pragma unroll
        for (int rr = 0; rr < 2; rr++) {
            int row = lt + rr * 30;
            if (row < TILE) {
                size_t g = (size_t)row * BF + cb;
                float fv = __ldg(f + g);
                float av = __ldg(alpha + g);
                float dv = __ldg(delta + g);
                shXL[0][row] = make_float2(__fadd_rn(__fmul_rn(av, DT_F), dv),
                                           logf(__fmul_rn(fv, DT_F)));
            }
        }
    }
    __syncthreads();

    for (int k = 0; k < NTILE; k++) {
        const int cur = k & 1, prv = cur ^ 1;
        if (scanMain || xScan) {
#pragma unroll 8
            for (int j = 0; j < TILE; j++) {
                float2 v = shXL[cur][j];
                carry = laestep(carry, v.x, v.y, sneg);
                shF[cur][j][tid] = __expf(carry);
            }
        } else if (isLoad) {
            if (k + 1 < NTILE) {
                const int tn = (k + 1) * TILE;
#pragma unroll
                for (int rr = 0; rr < 2; rr++) {
                    int row = lt + rr * 30;
                    if (row < TILE) {
                        size_t g = (size_t)(tn + row) * BF + cb;
                        float fv = __ldg(f + g);
                        float av = __ldg(alpha + g);
                        float dv = __ldg(delta + g);
                        shXL[prv][row] = make_float2(__fadd_rn(__fmul_rn(av, DT_F), dv),
                                                     logf(__fmul_rn(fv, DT_F)));
                    }
                }
            }
        } else if (mvAct && k > 0) {
            const int t0 = (k - 1) * TILE;
            for (int row = rg; row < TILE; row += 2) {
                size_t rb = ((size_t)(t0 + row) * BF + cb) * NOUT + jj;
                mv_row(shF[prv][row], jj, C, rb, til, Fout);
            }
        }
        __syncthreads();
    }

    // ---- epilogue ----
    if (scanMain || xScan) {
        hout[(size_t)cb * NTOT + tid] = carry;
    } else if (mvAct) {
        const int t0 = (NTILE - 1) * TILE;
        const int buf = (NTILE - 1) & 1;
        for (int row = rg; row < TILE; row += 2) {
            size_t rb = ((size_t)(t0 + row) * BF + cb) * NOUT + jj;
            mv_row(shF[buf][row], jj, C, rb, til, Fout);
        }
    }
}

// ---------------- launch --------------------------------------------------------
extern "C" void kernel_launch(void* const* d_in, const int* in_sizes, int n_in,
                              void* d_out, int out_size) {
    const float* f     = (const float*)d_in[0];
    const float* alpha = (const float*)d_in[1];
    const float* delta = (const float*)d_in[2];

    float* out  = (float*)d_out;
    size_t tsz  = (size_t)T_TOT * BF * NOUT;
    float* til  = out;
    float* hptr = out + tsz;
    float* Fo   = out + tsz + (size_t)BF * NTOT;

    init_kernel<<<NOUT, 96>>>();
    main_kernel<<<BF, 160>>>(f, alpha, delta, til, hptr, Fo);
}

// round 11
// speedup vs baseline: 1.0010x; 1.0006x over previous
#include <cuda_runtime.h>
#include <math.h>

#define BF     512
#define NTOT   66
#define NOUT   50
#define KK     8
#define T_TOT  2048
#define TILE   32
#define NTILE  (T_TOT / TILE)
#define DT_F   0.05f
#define FPAD   68

// ---------------- constant tables -------------------------------------------
__device__ float g_band[17][NOUT];   // g_band[d][j] = POST[j+d][j+8]
__device__ float g_sneg[NTOT];       // -(float)s_full[n]

// ---------------- fast init: one block per output column ---------------------
__global__ void init_kernel() {
    __shared__ double s[NTOT], dl[NTOT], dm[NTOT], du[NTOT];
    __shared__ double r[2][NTOT];
    const int j   = blockIdx.x;      // 0..49
    const int tid = threadIdx.x;     // 0..95
    const double c = pow(1000.0, 1.0 / 49.0);

    if (tid < NTOT) {
        double tv = 0.1 * pow(c, (double)(tid - KK));
        s[tid] = (double)KK / tv;
        if (j == 0) g_sneg[tid] = -(float)s[tid];
    }
    __syncthreads();
    if (tid < NTOT) {
        if (tid >= 1 && tid <= NTOT - 2) {
            double denom = s[tid + 1] - s[tid - 1];
            dl[tid] = -(1.0 / c) / denom;
            dm[tid] = (1.0 / c - c) / denom;
            du[tid] = c / denom;
        } else {
            dl[tid] = dm[tid] = du[tid] = 0.0;
        }
        r[0][tid] = (tid == j + KK) ? 1.0 : 0.0;
    }
    __syncthreads();

    for (int k = 1; k <= KK; k++) {
        int src = (k - 1) & 1, dst = k & 1;
        if (tid < NTOT) {
            double acc = r[src][tid] * dm[tid];
            if (tid > 0)        acc += r[src][tid - 1] * du[tid - 1];
            if (tid < NTOT - 1) acc += r[src][tid + 1] * dl[tid + 1];
            r[dst][tid] = acc;
        }
        __syncthreads();
    }
    if (tid < 17) {
        int m = j + KK;
        double tau = 0.1 * pow(c, (double)(m - KK));
        double w = tau * exp(9.0 * log(s[m]) - lgamma(9.0));
        g_band[tid][j] = (float)(r[0][j + tid] * w);
    }
}

// ---------------- bit-exact logaddexp step -----------------------------------
__device__ __forceinline__ float laestep(float carry, float x, float lf, float sneg) {
    float a  = __fadd_rn(carry, __fmul_rn(x, sneg));
    float am = fmaxf(a, lf);
    float dd = __fsub_rn(a, lf);
    return __fadd_rn(am, log1pf(expf(-fabsf(dd))));
}

// ---------------- packed f32x2 helpers ----------------------------------------
__device__ __forceinline__ unsigned long long pack2(float lo, float hi) {
    unsigned long long u;
    asm("mov.b64 %0, {%1, %2};" : "=l"(u) : "f"(lo), "f"(hi));
    return u;
}
__device__ __forceinline__ unsigned long long fma2(unsigned long long a,
                                                   unsigned long long b,
                                                   unsigned long long c) {
    unsigned long long d;
    asm("fma.rn.f32x2 %0, %1, %2, %3;" : "=l"(d) : "l"(a), "l"(b), "l"(c));
    return d;
}

// matvec body for one row: 17-tap banded dot for columns (jj, jj+1)
__device__ __forceinline__ void mv_row(const float* __restrict__ Fr, int jj,
                                       const unsigned long long* __restrict__ C,
                                       size_t rb, float* __restrict__ til,
                                       float* __restrict__ Fout) {
    float2 v[9];
#pragma unroll
    for (int i = 0; i < 9; i++) v[i] = *(const float2*)(Fr + jj + 2 * i);
    unsigned long long acc = 0ULL;
#pragma unroll
    for (int i = 0; i < 17; i++) {
        unsigned long long p = (i & 1)
            ? pack2(v[i >> 1].y, v[(i >> 1) + 1].x)
            : pack2(v[i >> 1].x, v[i >> 1].y);
        acc = fma2(p, C[i], acc);
    }
    float a0, a1;
    asm("mov.b64 {%0, %1}, %2;" : "=f"(a0), "=f"(a1) : "l"(acc));
    __stcs((float2*)(til  + rb), make_float2(a0, a1));
    __stcs((float2*)(Fout + rb), v[4]);   // F lanes jj+8, jj+9
}

// ---------------- fused scan + banded einsum, 1 chain per block ---------------
__global__ void __launch_bounds__(160) main_kernel(
    const float* __restrict__ f, const float* __restrict__ alpha,
    const float* __restrict__ delta,
    float* __restrict__ til, float* __restrict__ hout, float* __restrict__ Fout) {
    __shared__ float2 shXL[2][TILE];          // (x, lf)
    __shared__ float  shF[2][TILE][FPAD];

    const int cb  = blockIdx.x;
    const int tid = threadIdx.x;

    // ---- roles ----
    const bool scanMain = (tid < 64);                 // w0,w1: lanes 0..63
    const bool xScan    = (tid >= 64 && tid < 66);    // lanes 64,65
    const bool isLoad   = (tid >= 66 && tid < 96);    // 30 loaders in w2
    const int  lt       = tid - 66;
    const int  mt       = tid - 96;                   // w3,w4
    const bool mvAct    = (tid >= 96) && (mt < 50);
    const int  jj       = mvAct ? 2 * (mt % 25) : 0;
    const int  rg       = mvAct ? (mt / 25) : 0;      // row parity

    float sneg = 0.0f, carry = -INFINITY;
    if (scanMain)   sneg = g_sneg[tid];
    else if (xScan) sneg = g_sneg[tid];               // 64,65 directly

    unsigned long long C[17];
    if (mvAct) {
#pragma unroll
        for (int d = 0; d < 17; d++)
            C[d] = pack2(g_band[d][jj], g_band[d][jj + 1]);
    }

    // ---- prologue: loaders fill tile 0 ----
    if (isLoad) {
#pragma unroll
        for (int rr = 0; rr < 2; rr++) {
            int row = lt + rr * 30;
            if (row < TILE) {
                size_t g = (size_t)row * BF + cb;
                float fv = __ldg(f + g);
                float av = __ldg(alpha + g);
                float dv = __ldg(delta + g);
                shXL[0][row] = make_float2(__fadd_rn(__fmul_rn(av, DT_F), dv),
                                           logf(__fmul_rn(fv, DT_F)));
            }
        }
    }
    __syncthreads();

    for (int k = 0; k < NTILE; k++) {
        const int cur = k & 1, prv = cur ^ 1;
        if (scanMain || xScan) {
#pragma unroll 8
            for (int j = 0; j < TILE; j++) {
                float2 v = shXL[cur][j];
                carry = laestep(carry, v.x, v.y, sneg);
                shF[cur][j][tid] = __expf(carry);
            }
        } else if (isLoad) {
            if (k + 1 < NTILE) {
                const int tn = (k + 1) * TILE;
#pragma unroll
                for (int rr = 0; rr < 2; rr++) {
                    int row = lt + rr * 30;
                    if (row < TILE) {
                        size_t g = (size_t)(tn + row) * BF + cb;
                        float fv = __ldg(f + g);
                        float av = __ldg(alpha + g);
                        float dv = __ldg(delta + g);
                        shXL[prv][row] = make_float2(__fadd_rn(__fmul_rn(av, DT_F), dv),
                                                     logf(__fmul_rn(fv, DT_F)));
                    }
                }
            }
        } else if (mvAct && k > 0) {
            const int t0 = (k - 1) * TILE;
            for (int row = rg; row < TILE; row += 2) {
                size_t rb = ((size_t)(t0 + row) * BF + cb) * NOUT + jj;
                mv_row(shF[prv][row], jj, C, rb, til, Fout);
            }
        }
        __syncthreads();
    }

    // ---- epilogue ----
    if (scanMain || xScan) {
        hout[(size_t)cb * NTOT + tid] = carry;
    } else if (mvAct) {
        const int t0 = (NTILE - 1) * TILE;
        const int buf = (NTILE - 1) & 1;
        for (int row = rg; row < TILE; row += 2) {
            size_t rb = ((size_t)(t0 + row) * BF + cb) * NOUT + jj;
            mv_row(shF[buf][row], jj, C, rb, til, Fout);
        }
    }
}

// ---------------- launch --------------------------------------------------------
extern "C" void kernel_launch(void* const* d_in, const int* in_sizes, int n_in,
                              void* d_out, int out_size) {
    const float* f     = (const float*)d_in[0];
    const float* alpha = (const float*)d_in[1];
    const float* delta = (const float*)d_in[2];

    float* out  = (float*)d_out;
    size_t tsz  = (size_t)T_TOT * BF * NOUT;
    float* til  = out;
    float* hptr = out + tsz;
    float* Fo   = out + tsz + (size_t)BF * NTOT;

    init_kernel<<<NOUT, 96>>>();
    main_kernel<<<BF, 160>>>(f, alpha, delta, til, hptr, Fo);
}

// round 12
// speedup vs baseline: 1.0018x; 1.0009x over previous
#include <cuda_runtime.h>
#include <math.h>

#define BF     512
#define NTOT   66
#define NOUT   50
#define KK     8
#define T_TOT  2048
#define TILE   32
#define NTILE  (T_TOT / TILE)
#define DT_F   0.05f
#define FPAD   68

// ---------------- constant tables -------------------------------------------
__device__ float g_band[17][NOUT];   // g_band[d][j] = POST[j+d][j+8]
__device__ float g_sneg[NTOT];       // -(float)s_full[n]

// ---------------- fast init: one block per output column ---------------------
__global__ void init_kernel() {
    __shared__ double s[NTOT], dl[NTOT], dm[NTOT], du[NTOT];
    __shared__ double r[2][NTOT];
    const int j   = blockIdx.x;      // 0..49
    const int tid = threadIdx.x;     // 0..95
    const double c = pow(1000.0, 1.0 / 49.0);

    if (tid < NTOT) {
        double tv = 0.1 * pow(c, (double)(tid - KK));
        s[tid] = (double)KK / tv;
        if (j == 0) g_sneg[tid] = -(float)s[tid];
    }
    __syncthreads();
    if (tid < NTOT) {
        if (tid >= 1 && tid <= NTOT - 2) {
            double denom = s[tid + 1] - s[tid - 1];
            dl[tid] = -(1.0 / c) / denom;
            dm[tid] = (1.0 / c - c) / denom;
            du[tid] = c / denom;
        } else {
            dl[tid] = dm[tid] = du[tid] = 0.0;
        }
        r[0][tid] = (tid == j + KK) ? 1.0 : 0.0;
    }
    __syncthreads();

    for (int k = 1; k <= KK; k++) {
        int src = (k - 1) & 1, dst = k & 1;
        if (tid < NTOT) {
            double acc = r[src][tid] * dm[tid];
            if (tid > 0)        acc += r[src][tid - 1] * du[tid - 1];
            if (tid < NTOT - 1) acc += r[src][tid + 1] * dl[tid + 1];
            r[dst][tid] = acc;
        }
        __syncthreads();
    }
    if (tid < 17) {
        int m = j + KK;
        double tau = 0.1 * pow(c, (double)(m - KK));
        double w = tau * exp(9.0 * log(s[m]) - lgamma(9.0));
        g_band[tid][j] = (float)(r[0][j + tid] * w);
    }
}

// ---------------- bit-exact logaddexp step -----------------------------------
__device__ __forceinline__ float laestep(float carry, float x, float lf, float sneg) {
    float a  = __fadd_rn(carry, __fmul_rn(x, sneg));
    float am = fmaxf(a, lf);
    float dd = __fsub_rn(a, lf);
    return __fadd_rn(am, log1pf(expf(-fabsf(dd))));
}

// ---------------- packed f32x2 helpers ----------------------------------------
__device__ __forceinline__ unsigned long long pack2(float lo, float hi) {
    unsigned long long u;
    asm("mov.b64 %0, {%1, %2};" : "=l"(u) : "f"(lo), "f"(hi));
    return u;
}
__device__ __forceinline__ unsigned long long fma2(unsigned long long a,
                                                   unsigned long long b,
                                                   unsigned long long c) {
    unsigned long long d;
    asm("fma.rn.f32x2 %0, %1, %2, %3;" : "=l"(d) : "l"(a), "l"(b), "l"(c));
    return d;
}

// matvec body for one row: 17-tap banded dot for columns (jj, jj+1)
__device__ __forceinline__ void mv_row(const float* __restrict__ Fr, int jj,
                                       const unsigned long long* __restrict__ C,
                                       size_t rb, float* __restrict__ til,
                                       float* __restrict__ Fout) {
    float2 v[9];
#pragma unroll
    for (int i = 0; i < 9; i++) v[i] = *(const float2*)(Fr + jj + 2 * i);
    unsigned long long acc = 0ULL;
#pragma unroll
    for (int i = 0; i < 17; i++) {
        unsigned long long p = (i & 1)
            ? pack2(v[i >> 1].y, v[(i >> 1) + 1].x)
            : pack2(v[i >> 1].x, v[i >> 1].y);
        acc = fma2(p, C[i], acc);
    }
    float a0, a1;
    asm("mov.b64 {%0, %1}, %2;" : "=f"(a0), "=f"(a1) : "l"(acc));
    __stcs((float2*)(til  + rb), make_float2(a0, a1));
    __stcs((float2*)(Fout + rb), v[4]);   // F lanes jj+8, jj+9
}

// ---------------- fused scan + banded einsum, 1 chain per block ---------------
__global__ void __launch_bounds__(160) main_kernel(
    const float* __restrict__ f, const float* __restrict__ alpha,
    const float* __restrict__ delta,
    float* __restrict__ til, float* __restrict__ hout, float* __restrict__ Fout) {
    __shared__ float2 shXL[2][TILE];          // (x, lf)
    __shared__ float  shF[2][TILE][FPAD];

    const int cb  = blockIdx.x;
    const int tid = threadIdx.x;

    // ---- roles ----
    const bool scanMain = (tid < 64);                 // w0,w1: lanes 0..63
    const bool xScan    = (tid >= 64 && tid < 66);    // lanes 64,65
    const bool isLoad   = (tid >= 66 && tid < 96);    // 30 loaders in w2
    const int  lt       = tid - 66;
    const int  mt       = tid - 96;                   // w3,w4
    const bool mvAct    = (tid >= 96) && (mt < 50);
    const int  jj       = mvAct ? 2 * (mt % 25) : 0;
    const int  rg       = mvAct ? (mt / 25) : 0;      // row parity

    float sneg = 0.0f, carry = -INFINITY;
    if (scanMain)   sneg = g_sneg[tid];
    else if (xScan) sneg = g_sneg[tid];               // 64,65 directly

    unsigned long long C[17];
    if (mvAct) {
#pragma unroll
        for (int d = 0; d < 17; d++)
            C[d] = pack2(g_band[d][jj], g_band[d][jj + 1]);
    }

    // ---- prologue: loaders fill tile 0 ----
    if (isLoad) {
#pragma unroll
        for (int rr = 0; rr < 2; rr++) {
            int row = lt + rr * 30;
            if (row < TILE) {
                size_t g = (size_t)row * BF + cb;
                float fv = __ldg(f + g);
                float av = __ldg(alpha + g);
                float dv = __ldg(delta + g);
                shXL[0][row] = make_float2(__fadd_rn(__fmul_rn(av, DT_F), dv),
                                           logf(__fmul_rn(fv, DT_F)));
            }
        }
    }
    __syncthreads();

    for (int k = 0; k < NTILE; k++) {
        const int cur = k & 1, prv = cur ^ 1;
        if (scanMain || xScan) {
#pragma unroll 8
            for (int j = 0; j < TILE; j++) {
                float2 v = shXL[cur][j];
                carry = laestep(carry, v.x, v.y, sneg);
                shF[cur][j][tid] = __expf(carry);
            }
        } else if (isLoad) {
            if (k + 1 < NTILE) {
                const int tn = (k + 1) * TILE;
#pragma unroll
                for (int rr = 0; rr < 2; rr++) {
                    int row = lt + rr * 30;
                    if (row < TILE) {
                        size_t g = (size_t)(tn + row) * BF + cb;
                        float fv = __ldg(f + g);
                        float av = __ldg(alpha + g);
                        float dv = __ldg(delta + g);
                        shXL[prv][row] = make_float2(__fadd_rn(__fmul_rn(av, DT_F), dv),
                                                     logf(__fmul_rn(fv, DT_F)));
                    }
                }
            }
        } else if (mvAct && k > 0) {
            const int t0 = (k - 1) * TILE;
            for (int row = rg; row < TILE; row += 2) {
                size_t rb = ((size_t)(t0 + row) * BF + cb) * NOUT + jj;
                mv_row(shF[prv][row], jj, C, rb, til, Fout);
            }
        }
        __syncthreads();
    }

    // ---- epilogue ----
    if (scanMain || xScan) {
        hout[(size_t)cb * NTOT + tid] = carry;
    } else if (mvAct) {
        const int t0 = (NTILE - 1) * TILE;
        const int buf = (NTILE - 1) & 1;
        for (int row = rg; row < TILE; row += 2) {
            size_t rb = ((size_t)(t0 + row) * BF + cb) * NOUT + jj;
            mv_row(shF[buf][row], jj, C, rb, til, Fout);
        }
    }
}

// ---------------- launch --------------------------------------------------------
extern "C" void kernel_launch(void* const* d_in, const int* in_sizes, int n_in,
                              void* d_out, int out_size) {
    const float* f     = (const float*)d_in[0];
    const float* alpha = (const float*)d_in[1];
    const float* delta = (const float*)d_in[2];

    float* out  = (float*)d_out;
    size_t tsz  = (size_t)T_TOT * BF * NOUT;
    float* til  = out;
    float* hptr = out + tsz;
    float* Fo   = out + tsz + (size_t)BF * NTOT;

    init_kernel<<<NOUT, 96>>>();
    main_kernel<<<BF, 160>>>(f, alpha, delta, til, hptr, Fo);
}

// round 13
// speedup vs baseline: 1.0019x; 1.0001x over previous
#include <cuda_runtime.h>
#include <math.h>

#define BF     512
#define NTOT   66
#define NOUT   50
#define KK     8
#define T_TOT  2048
#define TILE   32
#define NTILE  (T_TOT / TILE)
#define DT_F   0.05f
#define FPAD   68

// ---------------- constant tables -------------------------------------------
__device__ float g_band[17][NOUT];   // g_band[d][j] = POST[j+d][j+8]
__device__ float g_sneg[NTOT];       // -(float)s_full[n]

// ---------------- fast init: one block per output column ---------------------
__global__ void init_kernel() {
    __shared__ double s[NTOT], dl[NTOT], dm[NTOT], du[NTOT];
    __shared__ double r[2][NTOT];
    const int j   = blockIdx.x;      // 0..49
    const int tid = threadIdx.x;     // 0..95
    const double c = pow(1000.0, 1.0 / 49.0);

    if (tid < NTOT) {
        double tv = 0.1 * pow(c, (double)(tid - KK));
        s[tid] = (double)KK / tv;
        if (j == 0) g_sneg[tid] = -(float)s[tid];
    }
    __syncthreads();
    if (tid < NTOT) {
        if (tid >= 1 && tid <= NTOT - 2) {
            double denom = s[tid + 1] - s[tid - 1];
            dl[tid] = -(1.0 / c) / denom;
            dm[tid] = (1.0 / c - c) / denom;
            du[tid] = c / denom;
        } else {
            dl[tid] = dm[tid] = du[tid] = 0.0;
        }
        r[0][tid] = (tid == j + KK) ? 1.0 : 0.0;
    }
    __syncthreads();

    for (int k = 1; k <= KK; k++) {
        int src = (k - 1) & 1, dst = k & 1;
        if (tid < NTOT) {
            double acc = r[src][tid] * dm[tid];
            if (tid > 0)        acc += r[src][tid - 1] * du[tid - 1];
            if (tid < NTOT - 1) acc += r[src][tid + 1] * dl[tid + 1];
            r[dst][tid] = acc;
        }
        __syncthreads();
    }
    if (tid < 17) {
        int m = j + KK;
        double tau = 0.1 * pow(c, (double)(m - KK));
        double w = tau * exp(9.0 * log(s[m]) - lgamma(9.0));
        g_band[tid][j] = (float)(r[0][j + tid] * w);
    }
}

// ---------------- bit-exact logaddexp step -----------------------------------
__device__ __forceinline__ float laestep(float carry, float x, float lf, float sneg) {
    float a  = __fadd_rn(carry, __fmul_rn(x, sneg));
    float am = fmaxf(a, lf);
    float dd = __fsub_rn(a, lf);
    return __fadd_rn(am, log1pf(expf(-fabsf(dd))));
}

// ---------------- packed f32x2 helpers ----------------------------------------
__device__ __forceinline__ unsigned long long pack2(float lo, float hi) {
    unsigned long long u;
    asm("mov.b64 %0, {%1, %2};" : "=l"(u) : "f"(lo), "f"(hi));
    return u;
}
__device__ __forceinline__ unsigned long long fma2(unsigned long long a,
                                                   unsigned long long b,
                                                   unsigned long long c) {
    unsigned long long d;
    asm("fma.rn.f32x2 %0, %1, %2, %3;" : "=l"(d) : "l"(a), "l"(b), "l"(c));
    return d;
}

// matvec body for one row: 17-tap banded dot for columns (jj, jj+1)
__device__ __forceinline__ void mv_row(const float* __restrict__ Fr, int jj,
                                       const unsigned long long* __restrict__ C,
                                       size_t rb, float* __restrict__ til,
                                       float* __restrict__ Fout) {
    float2 v[9];
#pragma unroll
    for (int i = 0; i < 9; i++) v[i] = *(const float2*)(Fr + jj + 2 * i);
    unsigned long long acc = 0ULL;
#pragma unroll
    for (int i = 0; i < 17; i++) {
        unsigned long long p = (i & 1)
            ? pack2(v[i >> 1].y, v[(i >> 1) + 1].x)
            : pack2(v[i >> 1].x, v[i >> 1].y);
        acc = fma2(p, C[i], acc);
    }
    float a0, a1;
    asm("mov.b64 {%0, %1}, %2;" : "=f"(a0), "=f"(a1) : "l"(acc));
    __stcs((float2*)(til  + rb), make_float2(a0, a1));
    __stcs((float2*)(Fout + rb), v[4]);   // F lanes jj+8, jj+9
}

// ---------------- fused scan + banded einsum, 1 chain per block ---------------
__global__ void __launch_bounds__(160) main_kernel(
    const float* __restrict__ f, const float* __restrict__ alpha,
    const float* __restrict__ delta,
    float* __restrict__ til, float* __restrict__ hout, float* __restrict__ Fout) {
    __shared__ float2 shXL[2][TILE];          // (x, lf)
    __shared__ float  shF[2][TILE][FPAD];

    const int cb  = blockIdx.x;
    const int tid = threadIdx.x;

    // ---- roles ----
    const bool scanMain = (tid < 64);                 // w0,w1: lanes 0..63
    const bool xScan    = (tid >= 64 && tid < 66);    // lanes 64,65
    const bool isLoad   = (tid >= 66 && tid < 96);    // 30 loaders in w2
    const int  lt       = tid - 66;
    const int  mt       = tid - 96;                   // w3,w4
    const bool mvAct    = (tid >= 96) && (mt < 50);
    const int  jj       = mvAct ? 2 * (mt % 25) : 0;
    const int  rg       = mvAct ? (mt / 25) : 0;      // row parity

    float sneg = 0.0f, carry = -INFINITY;
    if (scanMain)   sneg = g_sneg[tid];
    else if (xScan) sneg = g_sneg[tid];               // 64,65 directly

    unsigned long long C[17];
    if (mvAct) {
#pragma unroll
        for (int d = 0; d < 17; d++)
            C[d] = pack2(g_band[d][jj], g_band[d][jj + 1]);
    }

    // ---- prologue: loaders fill tile 0 ----
    if (isLoad) {
#pragma unroll
        for (int rr = 0; rr < 2; rr++) {
            int row = lt + rr * 30;
            if (row < TILE) {
                size_t g = (size_t)row * BF + cb;
                float fv = __ldg(f + g);
                float av = __ldg(alpha + g);
                float dv = __ldg(delta + g);
                shXL[0][row] = make_float2(__fadd_rn(__fmul_rn(av, DT_F), dv),
                                           logf(__fmul_rn(fv, DT_F)));
            }
        }
    }
    __syncthreads();

    for (int k = 0; k < NTILE; k++) {
        const int cur = k & 1, prv = cur ^ 1;
        if (scanMain || xScan) {
#pragma unroll 8
            for (int j = 0; j < TILE; j++) {
                float2 v = shXL[cur][j];
                carry = laestep(carry, v.x, v.y, sneg);
                shF[cur][j][tid] = __expf(carry);
            }
        } else if (isLoad) {
            if (k + 1 < NTILE) {
                const int tn = (k + 1) * TILE;
#pragma unroll
                for (int rr = 0; rr < 2; rr++) {
                    int row = lt + rr * 30;
                    if (row < TILE) {
                        size_t g = (size_t)(tn + row) * BF + cb;
                        float fv = __ldg(f + g);
                        float av = __ldg(alpha + g);
                        float dv = __ldg(delta + g);
                        shXL[prv][row] = make_float2(__fadd_rn(__fmul_rn(av, DT_F), dv),
                                                     logf(__fmul_rn(fv, DT_F)));
                    }
                }
            }
        } else if (mvAct && k > 0) {
            const int t0 = (k - 1) * TILE;
            for (int row = rg; row < TILE; row += 2) {
                size_t rb = ((size_t)(t0 + row) * BF + cb) * NOUT + jj;
                mv_row(shF[prv][row], jj, C, rb, til, Fout);
            }
        }
        __syncthreads();
    }

    // ---- epilogue ----
    if (scanMain || xScan) {
        hout[(size_t)cb * NTOT + tid] = carry;
    } else if (mvAct) {
        const int t0 = (NTILE - 1) * TILE;
        const int buf = (NTILE - 1) & 1;
        for (int row = rg; row < TILE; row += 2) {
            size_t rb = ((size_t)(t0 + row) * BF + cb) * NOUT + jj;
            mv_row(shF[buf][row], jj, C, rb, til, Fout);
        }
    }
}

// ---------------- launch --------------------------------------------------------
extern "C" void kernel_launch(void* const* d_in, const int* in_sizes, int n_in,
                              void* d_out, int out_size) {
    const float* f     = (const float*)d_in[0];
    const float* alpha = (const float*)d_in[1];
    const float* delta = (const float*)d_in[2];

    float* out  = (float*)d_out;
    size_t tsz  = (size_t)T_TOT * BF * NOUT;
    float* til  = out;
    float* hptr = out + tsz;
    float* Fo   = out + tsz + (size_t)BF * NTOT;

    init_kernel<<<NOUT, 96>>>();
    main_kernel<<<BF, 160>>>(f, alpha, delta, til, hptr, Fo);
}